// round 13
// baseline (speedup 1.0000x reference)
#include <cuda_runtime.h>
#include <cuda_bf16.h>

#define SEQ   1024
#define BATCH 512
#define NT    64
#define TPB   32    // ONE warp per batch: fwd+bwd chains interleaved

// Scratch (device globals; no allocation).
__device__ float g_llh[BATCH];
__device__ int   g_done;

__global__ void __launch_bounds__(TPB, 1)
crf_kernel(const float* __restrict__ em,
           const void* __restrict__ tags_raw,
           const int* __restrict__ mask,
           const float* __restrict__ startT,
           const float* __restrict__ endT,
           const float* __restrict__ trans,
           float* __restrict__ out)
{
    const int b    = blockIdx.x;      // one batch per block (one warp)
    const int lane = threadIdx.x;     // 0..31
    const int j0   = 2 * lane;        // owned tags (adjacent)
    const int j1   = 2 * lane + 1;

    // bf16 beta pairs, double-buffered, one buffer set per direction
    __shared__ __align__(16) __nv_bfloat162 shF[2][NT / 2];  // forward
    __shared__ __align__(16) __nv_bfloat162 shU[2][NT / 2];  // backward

    // ---- exp(transitions) bf16x2 packed over ROW PAIRS ----
    // fwd: coeff for tag j at row i = exp(trans[i][j])
    // bwd: coeff for tag j at row i = exp(trans[j][i])
    __nv_bfloat162 hF0[NT / 2], hF1[NT / 2], hB0[NT / 2], hB1[NT / 2];
#pragma unroll
    for (int k = 0; k < NT / 2; ++k) {
        hF0[k] = __floats2bfloat162_rn(__expf(trans[(2 * k) * NT + j0]),
                                       __expf(trans[(2 * k + 1) * NT + j0]));
        hF1[k] = __floats2bfloat162_rn(__expf(trans[(2 * k) * NT + j1]),
                                       __expf(trans[(2 * k + 1) * NT + j1]));
        hB0[k] = __floats2bfloat162_rn(__expf(trans[j0 * NT + 2 * k]),
                                       __expf(trans[j0 * NT + 2 * k + 1]));
        hB1[k] = __floats2bfloat162_rn(__expf(trans[j1 * NT + 2 * k]),
                                       __expf(trans[j1 * NT + 2 * k + 1]));
    }

    // ---- sequence length (mask monotone: mask[t] = t < length) ----
    int cnt = 0;
    for (int t = lane; t < SEQ; t += 32)
        cnt += mask[t * BATCH + b];
#pragma unroll
    for (int o = 16; o > 0; o >>= 1)
        cnt += __shfl_xor_sync(0xffffffffu, cnt, o);
    const int length = cnt;

    const int m  = (length - 1) >> 1;   // meeting point
    const int nf = m;                   // fwd steps
    const int nb = (length - 1) - m;    // bwd steps (= nf or nf+1)

    // ---- numerator ----
    float gnum;
    {
        const int*       t32 = (const int*)tags_raw;
        const long long* t64 = (const long long*)tags_raw;
        bool is64 = true;
#pragma unroll
        for (int k = 0; k < 16; ++k)
            is64 = is64 && (t32[2 * k * 1031 + 1] == 0);

        float num = 0.f;
        if (is64) {
            for (int t = 1 + lane; t < length; t += 32) {
                const int pt = (int)t64[(t - 1) * BATCH + b];
                const int ct = (int)t64[t * BATCH + b];
                num += trans[pt * NT + ct] + em[(t * BATCH + b) * NT + ct];
            }
        } else {
            for (int t = 1 + lane; t < length; t += 32) {
                const int pt = t32[(t - 1) * BATCH + b];
                const int ct = t32[t * BATCH + b];
                num += trans[pt * NT + ct] + em[(t * BATCH + b) * NT + ct];
            }
        }
#pragma unroll
        for (int o = 16; o > 0; o >>= 1)
            num += __shfl_xor_sync(0xffffffffu, num, o);
        const int t0 = is64 ? (int)t64[b] : t32[b];
        const int tl = is64 ? (int)t64[(length - 1) * BATCH + b]
                            : t32[(length - 1) * BATCH + b];
        gnum = num + startT[t0] + em[b * NT + t0] + endT[tl];
    }

    // ---- em streams: fwd ascending from row 0, bwd descending from L-1 ----
    const float2* __restrict__ em2 = (const float2*)em;
    const int sV  = BATCH * (NT / 2);                  // row stride, float2
    const int bF  = b * (NT / 2) + lane;               // fwd base (row 0)
    const int bB  = (length - 1) * sV + b * (NT / 2) + lane;  // bwd base

    {
        const float2 ef = em2[bF];
        const float2 eb = em2[bB];
        shF[0][lane] = __floats2bfloat162_rn(__expf(startT[j0] + ef.x),
                                             __expf(startT[j1] + ef.y));
        shU[0][lane] = __floats2bfloat162_rn(__expf(endT[j0] + eb.x),
                                             __expf(endT[j1] + eb.y));
    }

    const float2 f2z = make_float2(0.f, 0.f);
    float2 pf0 = (1 <= nf) ? em2[bF + 1 * sV] : f2z;
    float2 pf1 = (2 <= nf) ? em2[bF + 2 * sV] : f2z;
    float2 pf2 = (3 <= nf) ? em2[bF + 3 * sV] : f2z;
    float2 pf3 = (4 <= nf) ? em2[bF + 4 * sV] : f2z;
    float2 pb0 = (1 <= nb) ? em2[bB - 1 * sV] : f2z;
    float2 pb1 = (2 <= nb) ? em2[bB - 2 * sV] : f2z;
    float2 pb2 = (3 <= nb) ? em2[bB - 3 * sV] : f2z;
    float2 pb3 = (4 <= nb) ? em2[bB - 4 * sV] : f2z;

    int ktf = 0, ktb = 0;
    __syncwarp();

    const __nv_bfloat162 hz = __floats2bfloat162_rn(0.f, 0.f);

    // One direction-step: 64 HFMA2 over 8 LDS.128, fp32 epilogue.
#define DSTEP(SH, HT0, HT1, PP, EXLO, EXHI, RENORM, KT) do {                 \
        const uint4* __restrict__ e4 = (const uint4*)SH[PP];                  \
        float scale_ = 1.0f;                                                  \
        if (RENORM) {                                                         \
            const unsigned w0 = *(const unsigned*)&SH[PP][0];                 \
            const int kk = (int)((w0 >> 7) & 0xFFu) - 127;                    \
            scale_ = __int_as_float((127 - kk) << 23);                        \
            KT += kk;                                                         \
        }                                                                     \
        __nv_bfloat162 a00 = hz, a01 = hz, a02 = hz, a03 = hz;                \
        __nv_bfloat162 a10 = hz, a11 = hz, a12 = hz, a13 = hz;                \
        _Pragma("unroll")                                                     \
        for (int k = 0; k < 8; ++k) {                                         \
            const uint4 q = e4[k];                                            \
            const __nv_bfloat162 q0 = *(const __nv_bfloat162*)&q.x;           \
            const __nv_bfloat162 q1 = *(const __nv_bfloat162*)&q.y;           \
            const __nv_bfloat162 q2 = *(const __nv_bfloat162*)&q.z;           \
            const __nv_bfloat162 q3 = *(const __nv_bfloat162*)&q.w;           \
            a00 = __hfma2(q0, HT0[4 * k + 0], a00);                           \
            a10 = __hfma2(q0, HT1[4 * k + 0], a10);                           \
            a01 = __hfma2(q1, HT0[4 * k + 1], a01);                           \
            a11 = __hfma2(q1, HT1[4 * k + 1], a11);                           \
            a02 = __hfma2(q2, HT0[4 * k + 2], a02);                           \
            a12 = __hfma2(q2, HT1[4 * k + 2], a12);                           \
            a03 = __hfma2(q3, HT0[4 * k + 3], a03);                           \
            a13 = __hfma2(q3, HT1[4 * k + 3], a13);                           \
        }                                                                     \
        const __nv_bfloat162 s0 =                                             \
            __hadd2(__hadd2(a00, a01), __hadd2(a02, a03));                    \
        const __nv_bfloat162 s1 =                                             \
            __hadd2(__hadd2(a10, a11), __hadd2(a12, a13));                    \
        const float2 f0 = __bfloat1622float2(s0);                             \
        const float2 f1 = __bfloat1622float2(s1);                             \
        const float b0_ = (f0.x + f0.y) * ((EXLO) * scale_);                  \
        const float b1_ = (f1.x + f1.y) * ((EXHI) * scale_);                  \
        SH[(PP) ^ 1][lane] = __floats2bfloat162_rn(b0_, b1_);                 \
    } while (0)

#define FSTEP(PP, EL, EH, RN) DSTEP(shF, hF0, hF1, PP, EL, EH, RN, ktf)
#define BSTEP(PP, EL, EH, RN) DSTEP(shU, hB0, hB1, PP, EL, EH, RN, ktb)

    int v = 1;
    for (; v + 3 <= nf; v += 4) {
        // prefetch next group's emissions (both streams, MLP=8)
        const float2 qf0 = (v + 4 <= nf) ? em2[bF + (v + 4) * sV] : f2z;
        const float2 qf1 = (v + 5 <= nf) ? em2[bF + (v + 5) * sV] : f2z;
        const float2 qf2 = (v + 6 <= nf) ? em2[bF + (v + 6) * sV] : f2z;
        const float2 qf3 = (v + 7 <= nf) ? em2[bF + (v + 7) * sV] : f2z;
        const float2 qb0 = (v + 4 <= nb) ? em2[bB - (v + 4) * sV] : f2z;
        const float2 qb1 = (v + 5 <= nb) ? em2[bB - (v + 5) * sV] : f2z;
        const float2 qb2 = (v + 6 <= nb) ? em2[bB - (v + 6) * sV] : f2z;
        const float2 qb3 = (v + 7 <= nb) ? em2[bB - (v + 7) * sV] : f2z;

        const float ef0l = __expf(pf0.x), ef0h = __expf(pf0.y);
        const float eb0l = __expf(pb0.x), eb0h = __expf(pb0.y);
        const float ef1l = __expf(pf1.x), ef1h = __expf(pf1.y);
        const float eb1l = __expf(pb1.x), eb1h = __expf(pb1.y);
        const float ef2l = __expf(pf2.x), ef2h = __expf(pf2.y);
        const float eb2l = __expf(pb2.x), eb2h = __expf(pb2.y);
        const float ef3l = __expf(pf3.x), ef3h = __expf(pf3.y);
        const float eb3l = __expf(pb3.x), eb3h = __expf(pb3.y);

        // super-steps: fwd + bwd interleaved, one syncwarp per super-step
        FSTEP(0, ef0l, ef0h, true);  BSTEP(0, eb0l, eb0h, true);  __syncwarp();
        FSTEP(1, ef1l, ef1h, false); BSTEP(1, eb1l, eb1h, false); __syncwarp();
        FSTEP(0, ef2l, ef2h, false); BSTEP(0, eb2l, eb2h, false); __syncwarp();
        FSTEP(1, ef3l, ef3h, false); BSTEP(1, eb3l, eb3h, false); __syncwarp();

        pf0 = qf0; pf1 = qf1; pf2 = qf2; pf3 = qf3;
        pb0 = qb0; pb1 = qb1; pb2 = qb2; pb3 = qb3;
    }
    // tails (v odd; nf <= v+2, nb <= nf+1 <= v+3)
    if (v     <= nf) FSTEP(0, __expf(pf0.x), __expf(pf0.y), false);
    if (v     <= nb) BSTEP(0, __expf(pb0.x), __expf(pb0.y), false);
    __syncwarp();
    if (v + 1 <= nf) FSTEP(1, __expf(pf1.x), __expf(pf1.y), false);
    if (v + 1 <= nb) BSTEP(1, __expf(pb1.x), __expf(pb1.y), false);
    __syncwarp();
    if (v + 2 <= nf) FSTEP(0, __expf(pf2.x), __expf(pf2.y), false);
    if (v + 2 <= nb) BSTEP(0, __expf(pb2.x), __expf(pb2.y), false);
    __syncwarp();
    if (v + 3 <= nb) BSTEP(1, __expf(pb3.x), __expf(pb3.y), false);
    __syncwarp();

#undef FSTEP
#undef BSTEP
#undef DSTEP

    // ---- combine in-warp: Z = sum_j F_m(j) * u_m(j) * exp(-em_m(j)) ----
    {
        const float2 Fv = __bfloat1622float2(shF[nf & 1][lane]);
        const float2 Uv = __bfloat1622float2(shU[nb & 1][lane]);
        const float2 emm = em2[m * sV + b * (NT / 2) + lane];
        float s = Fv.x * Uv.x * __expf(-emm.x)
                + Fv.y * Uv.y * __expf(-emm.y);
#pragma unroll
        for (int o = 16; o > 0; o >>= 1)
            s += __shfl_xor_sync(0xffffffffu, s, o);

        if (lane == 0) {
            const double denom = (double)(ktf + ktb) * 0.6931471805599453
                               + (double)logf(s);
            g_llh[b] = (float)((double)gnum - denom);
        }
    }

    // ---- final reduction by the last warp ----
    __threadfence();
    int last = 0;
    if (lane == 0)
        last = (atomicAdd(&g_done, 1) == BATCH - 1) ? 1 : 0;
    last = __shfl_sync(0xffffffffu, last, 0);

    if (last) {
        double acc = 0.0;
#pragma unroll
        for (int k = 0; k < BATCH / 32; ++k)       // fixed order: 16 each
            acc += (double)g_llh[lane + k * 32];
#pragma unroll
        for (int o = 16; o > 0; o >>= 1)
            acc += __shfl_xor_sync(0xffffffffu, acc, o);
        if (lane == 0) {
            out[0] = (float)acc;
            atomicExch(&g_done, 0);    // reset for next replay
        }
    }
}

extern "C" void kernel_launch(void* const* d_in, const int* in_sizes, int n_in,
                              void* d_out, int out_size)
{
    const float* em     = (const float*)d_in[0];
    const void*  tags   = (const void*)d_in[1];
    const int*   mask   = (const int*)d_in[2];
    const float* startT = (const float*)d_in[3];
    const float* endT   = (const float*)d_in[4];
    const float* trans  = (const float*)d_in[5];
    float* out = (float*)d_out;

    crf_kernel<<<BATCH, TPB>>>(em, tags, mask, startT, endT, trans, out);
}

// round 14
// speedup vs baseline: 1.2314x; 1.2314x over previous
#include <cuda_runtime.h>
#include <cuda_bf16.h>

#define SEQ   1024
#define BATCH 512
#define NT    64
#define TPB   64    // 2 warps; thread j = tag j

// Scratch (device globals; no allocation).
__device__ float g_vec[2][BATCH][NT];  // [0]=forward F~, [1]=backward u
__device__ int   g_kt[2][BATCH];
__device__ float g_num[BATCH];
__device__ int   g_pair[BATCH];
__device__ float g_llh[BATCH];
__device__ int   g_done;

__global__ void __launch_bounds__(TPB)
crf_kernel(const float* __restrict__ em,
           const void* __restrict__ tags_raw,
           const int* __restrict__ mask,
           const float* __restrict__ startT,
           const float* __restrict__ endT,
           const float* __restrict__ trans,
           float* __restrict__ out)
{
    const int bb   = blockIdx.x;
    const int b    = bb >> 1;         // batch
    const int half = bb & 1;          // 0 = forward, 1 = backward
    const int j    = threadIdx.x;     // tag 0..63 (one tag per thread)
    const int lane = j & 31;
    const int warp = j >> 5;

    __shared__ __align__(16) __nv_bfloat16 shB[2][NT];  // beta, double-buffered
    __shared__ float sh_red[2];
    __shared__ int   sh_len[2];
    __shared__ int   sh_flag;

    // ---- exp(transitions) bf16x2 over ROW PAIRS, for MY tag j ----
    // fwd: coeff at row i = exp(trans[i][j]); bwd: exp(trans[j][i])
    __nv_bfloat162 hT[NT / 2];
    if (half == 0) {
#pragma unroll
        for (int k = 0; k < NT / 2; ++k)
            hT[k] = __floats2bfloat162_rn(__expf(trans[(2 * k) * NT + j]),
                                          __expf(trans[(2 * k + 1) * NT + j]));
    } else {
#pragma unroll
        for (int k = 0; k < NT / 2; ++k)
            hT[k] = __floats2bfloat162_rn(__expf(trans[j * NT + 2 * k]),
                                          __expf(trans[j * NT + 2 * k + 1]));
    }

    // ---- sequence length (mask monotone: mask[t] = t < length) ----
    int cnt = 0;
#pragma unroll
    for (int t = j; t < SEQ; t += TPB)
        cnt += mask[t * BATCH + b];
#pragma unroll
    for (int o = 16; o > 0; o >>= 1)
        cnt += __shfl_xor_sync(0xffffffffu, cnt, o);
    if (lane == 0) sh_len[warp] = cnt;
    __syncthreads();
    const int length = sh_len[0] + sh_len[1];

    const int m = (length - 1) >> 1;           // meeting point
    const int n = half ? (length - 1 - m) : m; // my step count (block-uniform)

    // ---- numerator (forward block only) ----
    if (half == 0) {
        const int*       t32 = (const int*)tags_raw;
        const long long* t64 = (const long long*)tags_raw;
        bool is64 = true;
#pragma unroll
        for (int k = 0; k < 16; ++k)
            is64 = is64 && (t32[2 * k * 1031 + 1] == 0);

        float num = 0.f;
        if (is64) {
            for (int t = 1 + j; t < length; t += TPB) {
                const int pt = (int)t64[(t - 1) * BATCH + b];
                const int ct = (int)t64[t * BATCH + b];
                num += trans[pt * NT + ct] + em[(t * BATCH + b) * NT + ct];
            }
        } else {
            for (int t = 1 + j; t < length; t += TPB) {
                const int pt = t32[(t - 1) * BATCH + b];
                const int ct = t32[t * BATCH + b];
                num += trans[pt * NT + ct] + em[(t * BATCH + b) * NT + ct];
            }
        }
#pragma unroll
        for (int o = 16; o > 0; o >>= 1)
            num += __shfl_xor_sync(0xffffffffu, num, o);
        if (lane == 0) sh_red[warp] = num;
        __syncthreads();
        if (j == 0) {
            const int t0 = is64 ? (int)t64[b] : t32[b];
            const int tl = is64 ? (int)t64[(length - 1) * BATCH + b]
                                : t32[(length - 1) * BATCH + b];
            g_num[b] = sh_red[0] + sh_red[1]
                     + startT[t0] + em[b * NT + t0] + endT[tl];
        }
        __syncthreads();
    }

    // ---- em stream: fwd ascending from 0, bwd descending from L-1 ----
    const int row0   = half ? (length - 1) : 0;
    const int stride = half ? -(BATCH * NT) : (BATCH * NT);
    const int base   = (row0 * BATCH + b) * NT + j;

    shB[0][j] = __float2bfloat16(half ? __expf(endT[j] + em[base])
                                      : __expf(startT[j] + em[base]));

    float p0 = (1 <= n) ? em[base + 1 * stride] : 0.f;
    float p1 = (2 <= n) ? em[base + 2 * stride] : 0.f;
    float p2 = (3 <= n) ? em[base + 3 * stride] : 0.f;
    float p3 = (4 <= n) ? em[base + 4 * stride] : 0.f;

    int ktot = 0;
    __syncthreads();

    const __nv_bfloat162 hz = __floats2bfloat162_rn(0.f, 0.f);

    // One step for MY tag: 8 LDS.128, 32 HFMA2, fp32 epilogue, one bar.
#define STEP(PP, EXV, RENORM) do {                                          \
        const uint4* __restrict__ e4 = (const uint4*)shB[PP];                \
        float scale_ = 1.0f;                                                 \
        if (RENORM) {                                                        \
            const unsigned short w0 =                                        \
                *(const unsigned short*)&shB[PP][0];                         \
            const int kk = (int)((w0 >> 7) & 0xFFu) - 127;                   \
            scale_ = __int_as_float((127 - kk) << 23);                       \
            ktot += kk;                                                      \
        }                                                                    \
        __nv_bfloat162 a0 = hz, a1 = hz, a2 = hz, a3 = hz;                   \
        _Pragma("unroll")                                                    \
        for (int k = 0; k < 8; ++k) {          /* beta 8k .. 8k+7 */         \
            const uint4 q = e4[k];                                           \
            a0 = __hfma2(*(const __nv_bfloat162*)&q.x, hT[4 * k + 0], a0);   \
            a1 = __hfma2(*(const __nv_bfloat162*)&q.y, hT[4 * k + 1], a1);   \
            a2 = __hfma2(*(const __nv_bfloat162*)&q.z, hT[4 * k + 2], a2);   \
            a3 = __hfma2(*(const __nv_bfloat162*)&q.w, hT[4 * k + 3], a3);   \
        }                                                                    \
        const __nv_bfloat162 s2 = __hadd2(__hadd2(a0, a1), __hadd2(a2, a3)); \
        const float2 f = __bfloat1622float2(s2);                             \
        const float bn = (f.x + f.y) * ((EXV) * scale_);                     \
        shB[(PP) ^ 1][j] = __float2bfloat16(bn);                             \
        __syncthreads();                                                     \
    } while (0)

    int v = 1;   // group base odd => compile-time buffer parities
    for (; v + 3 <= n; v += 4) {
        const float q0 = (v + 4 <= n) ? em[base + (v + 4) * stride] : 0.f;
        const float q1 = (v + 5 <= n) ? em[base + (v + 5) * stride] : 0.f;
        const float q2 = (v + 6 <= n) ? em[base + (v + 6) * stride] : 0.f;
        const float q3 = (v + 7 <= n) ? em[base + (v + 7) * stride] : 0.f;

        const float ex0 = __expf(p0);
        const float ex1 = __expf(p1);
        const float ex2 = __expf(p2);
        const float ex3 = __expf(p3);

        STEP(0, ex0, true);
        STEP(1, ex1, false);
        STEP(0, ex2, false);
        STEP(1, ex3, false);

        p0 = q0; p1 = q1; p2 = q2; p3 = q3;
    }
    // tail: guards are block-uniform (n uniform) -> barriers legal
    if (v     <= n) STEP(0, __expf(p0), false);
    if (v + 1 <= n) STEP(1, __expf(p1), false);
    if (v + 2 <= n) STEP(0, __expf(p2), false);
#undef STEP

    // ---- publish my half ----
    g_vec[half][b][j] = __bfloat162float(shB[n & 1][j]);
    if (j == 0) g_kt[half][b] = ktot;

    __threadfence();
    if (j == 0)
        sh_flag = (atomicAdd(&g_pair[b], 1) == 1) ? 1 : 0;
    __syncthreads();

    if (sh_flag) {
        __threadfence();   // acquire side
        // Z = sum_j F_m(j) * u_m(j) * exp(-em_m(j))
        float s = g_vec[0][b][j] * g_vec[1][b][j]
                * __expf(-em[(m * BATCH + b) * NT + j]);
#pragma unroll
        for (int o = 16; o > 0; o >>= 1)
            s += __shfl_xor_sync(0xffffffffu, s, o);
        if (lane == 0) sh_red[warp] = s;
        __syncthreads();

        if (j == 0) {
            const int kt = g_kt[0][b] + g_kt[1][b];
            const double denom = (double)kt * 0.6931471805599453
                               + (double)logf(sh_red[0] + sh_red[1]);
            g_llh[b] = (float)((double)g_num[b] - denom);
            g_pair[b] = 0;                 // reset for next replay
        }

        // ---- final reduction by the last combiner ----
        __threadfence();
        if (j == 0)
            sh_flag = (atomicAdd(&g_done, 1) == BATCH - 1) ? 2 : 0;
        __syncthreads();

        if (sh_flag == 2) {
            __shared__ double red[TPB];
            double acc = 0.0;
#pragma unroll
            for (int k = 0; k < BATCH / TPB; ++k)      // fixed order: 8 each
                acc += (double)g_llh[j + k * TPB];
            red[j] = acc;
            __syncthreads();
#pragma unroll
            for (int o = TPB / 2; o > 0; o >>= 1) {
                if (j < o) red[j] += red[j + o];
                __syncthreads();
            }
            if (j == 0) {
                out[0] = (float)red[0];
                atomicExch(&g_done, 0);    // reset for next replay
            }
        }
    }
}

extern "C" void kernel_launch(void* const* d_in, const int* in_sizes, int n_in,
                              void* d_out, int out_size)
{
    const float* em     = (const float*)d_in[0];
    const void*  tags   = (const void*)d_in[1];
    const int*   mask   = (const int*)d_in[2];
    const float* startT = (const float*)d_in[3];
    const float* endT   = (const float*)d_in[4];
    const float* trans  = (const float*)d_in[5];
    float* out = (float*)d_out;

    crf_kernel<<<2 * BATCH, TPB>>>(em, tags, mask, startT, endT, trans, out);
}